// round 8
// baseline (speedup 1.0000x reference)
#include <cuda_runtime.h>
#include <cuda_bf16.h>
#include <math.h>
#include <cstdint>

#define Nn   50000
#define Ee   800000
#define Ff   32
#define NINVc 128
#define NLc  4
#define Hc   64
#define Gc   2048
#define EPSf 1e-6f
#define NT   (Ee/128)   // 6250 tiles of 128 edges

// ---------------- device scratch (no allocs allowed) ----------------
__device__ __align__(16) float  g_edge_in[Ee*5];
__device__ float  g_u[Ee*3];
__device__ int    g_src[Ee];
__device__ int    g_dst[Ee];
__device__ __align__(16) float  g_s[Nn*Ff];
__device__ __align__(16) float  g_v0[Nn*Ff];
__device__ __align__(16) float  g_v1[Nn*Ff];
__device__ __align__(16) float  g_v2[Nn*Ff];
__device__ float4 g_acc[Nn*Ff];       // {ms, mv0, mv1, mv2}
__device__ float  g_invden[Nn];
__device__ float  g_cnt[Nn];
__device__ float  g_xg[Gc*NINVc];
__device__ float  g_gcnt[Gc];
__device__ float  g_xgp[Gc*NINVc];
__device__ float  g_z1[Gc*NINVc];
__device__ float  g_mean1[NINVc], g_rstd1[NINVc], g_mean2[NINVc], g_rstd2[NINVc];

__device__ __forceinline__ float elu1(float x) { return x > 0.f ? x : expm1f(x); }
__device__ __forceinline__ float elu_fast(float x) { return x > 0.f ? x : (__expf(x) - 1.f); }

// warp-level bf16 mma (sm_80+ baseline PTX; works on plain sm_103 target)
__device__ __forceinline__ void mma16816(float* d, const uint32_t* a, const uint32_t* b) {
    asm volatile(
        "mma.sync.aligned.m16n8k16.row.col.f32.bf16.bf16.f32 "
        "{%0,%1,%2,%3}, {%4,%5,%6,%7}, {%8,%9}, {%0,%1,%2,%3};"
        : "+f"(d[0]), "+f"(d[1]), "+f"(d[2]), "+f"(d[3])
        : "r"(a[0]), "r"(a[1]), "r"(a[2]), "r"(a[3]), "r"(b[0]), "r"(b[1]));
}
__device__ __forceinline__ void bf16split(float x, uint16_t& h, uint16_t& l) {
    __nv_bfloat16 hb = __float2bfloat16_rn(x);
    float r = x - __bfloat162float(hb);
    __nv_bfloat16 lb = __float2bfloat16_rn(r);
    h = __bfloat16_as_ushort(hb);
    l = __bfloat16_as_ushort(lb);
}

// ---------------- zero / preprocessing ----------------
__global__ void k_zero_all() {
    int i = blockIdx.x*blockDim.x + threadIdx.x;
    if (i < Nn*Ff) { g_acc[i] = make_float4(0.f,0.f,0.f,0.f); return; }
    i -= Nn*Ff;
    if (i < Nn) { g_cnt[i] = 0.f; return; }
    i -= Nn;
    if (i < Gc) { g_gcnt[i] = 0.f; return; }
    i -= Gc;
    if (i < Gc*NINVc) g_xg[i] = 0.f;
}
__global__ void k_edge_prep(const float* __restrict__ pos,
                            const int* __restrict__ ei,
                            const float* __restrict__ eattr) {
    int e = blockIdx.x*blockDim.x + threadIdx.x;
    if (e >= Ee) return;
    int src = ei[e];
    int dst = ei[Ee + e];
    float dx = pos[dst*3+0] - pos[src*3+0];
    float dy = pos[dst*3+1] - pos[src*3+1];
    float dz = pos[dst*3+2] - pos[src*3+2];
    float d  = sqrtf(dx*dx + dy*dy + dz*dz + EPSf);
    float inv = 1.0f/d;
    g_edge_in[e*5+0] = d;
    g_edge_in[e*5+1] = eattr[e*4+0];
    g_edge_in[e*5+2] = eattr[e*4+1];
    g_edge_in[e*5+3] = eattr[e*4+2];
    g_edge_in[e*5+4] = eattr[e*4+3];
    g_u[e*3+0] = dx*inv;
    g_u[e*3+1] = dy*inv;
    g_u[e*3+2] = dz*inv;
    g_src[e] = src;
    g_dst[e] = dst;
    atomicAdd(&g_cnt[dst], 1.f);
}
__global__ void k_gcnt(const int* __restrict__ batch) {
    int n = blockIdx.x*blockDim.x + threadIdx.x;
    if (n < Nn) atomicAdd(&g_gcnt[batch[n]], 1.f);
}
__global__ void k_invden() {
    int n = blockIdx.x*blockDim.x + threadIdx.x;
    if (n < Nn) g_invden[n] = 1.f / fmaxf(g_cnt[n], 1.f);
}
__global__ void k_embed(const float* __restrict__ x, const float* __restrict__ pos,
                        const float* __restrict__ W_es, const float* __restrict__ b_es,
                        const float* __restrict__ W_ev) {
    int idx = blockIdx.x*blockDim.x + threadIdx.x;
    if (idx >= Nn*Ff) return;
    int n = idx >> 5, f = idx & 31;
    const float* xr = x + n*5;
    float s = b_es[f], ev = 0.f;
    #pragma unroll
    for (int k = 0; k < 5; k++) {
        float xv = xr[k];
        s  += xv * W_es[k*Ff + f];
        ev += xv * W_ev[k*Ff + f];
    }
    g_s[idx] = s;
    float p0 = pos[n*3+0], p1 = pos[n*3+1], p2 = pos[n*3+2];
    g_v0[idx] = ev*p0;
    g_v1[idx] = ev*p1;
    g_v2[idx] = ev*p2;
}

// ---------------- HMMA fused message kernel (M=32/warp, fragment-direct MLP1) ----------------
// Tile = 128 edges, 128 threads (4 warps). Warp w owns edges [w*32, w*32+32) = 2 m16 tiles.
// No A smem: each lane computes MLP1 for exactly the fragment elements it owns.
// B (W2^T hi/lo) [96][72 pad] smem; 3-pass split mma (Ah*Bh + Ah*Bl + Al*Bh).
#define OFF_BH   0
#define OFF_BL   13824
#define OFF_EINS 27648
#define OFF_US   30208
#define OFF_SRC  31744
#define OFF_DST  32256
#define OFF_W1S  32768
#define OFF_B1S  34048
#define OFF_B2S  34304
#define TC_SMEM  34688
__global__ void __launch_bounds__(128, 3)
k_msg_mma(const float* __restrict__ W1, const float* __restrict__ b1,
          const float* __restrict__ W2, const float* __restrict__ b2) {
    extern __shared__ char smc[];
    uint16_t* BH = (uint16_t*)(smc + OFF_BH);
    uint16_t* BL = (uint16_t*)(smc + OFF_BL);
    float* eins = (float*)(smc + OFF_EINS);
    float* us   = (float*)(smc + OFF_US);
    int* srcs   = (int*)(smc + OFF_SRC);
    int* dsts   = (int*)(smc + OFF_DST);
    float* w1s  = (float*)(smc + OFF_W1S);
    float* b1s  = (float*)(smc + OFF_B1S);
    float* b2s  = (float*)(smc + OFF_B2S);
    const uint32_t* BH32 = (const uint32_t*)(smc + OFF_BH);
    const uint32_t* BL32 = (const uint32_t*)(smc + OFF_BL);

    int tid = threadIdx.x;
    // stage weights once per block
    for (int i = tid; i < 320; i += 128) w1s[i] = W1[i];
    for (int i = tid; i < 64;  i += 128) b1s[i] = b1[i];
    for (int i = tid; i < 96;  i += 128) b2s[i] = b2[i];
    for (int idx = tid; idx < 96*64; idx += 128) {
        int n = idx >> 6, k = idx & 63;
        uint16_t h, l; bf16split(W2[k*96 + n], h, l);
        BH[n*72 + k] = h;
        BL[n*72 + k] = l;
    }

    int lane = tid & 31, warp = tid >> 5;
    int wb = warp * 32;
    int r = lane >> 2, q = lane & 3;

    for (int tile = blockIdx.x; tile < NT; tile += gridDim.x) {
        __syncthreads();   // prior tile's smem reads done (weight staging on 1st iter)
        int e0 = tile * 128;
        for (int i = tid; i < 640; i += 128) eins[i] = g_edge_in[e0*5 + i];
        for (int i = tid; i < 384; i += 128) us[i]   = g_u[e0*3 + i];
        srcs[tid] = g_src[e0 + tid];
        dsts[tid] = g_dst[e0 + tid];
        __syncthreads();

        // preload edge inputs for this lane's 4 rows
        float xv[4][5];
        #pragma unroll
        for (int m = 0; m < 4; m++) {
            int row = wb + r + m*8;
            #pragma unroll
            for (int i = 0; i < 5; i++) xv[m][i] = eins[row*5 + i];
        }

        // acc init with bias (both m16 tiles share columns)
        float acc[12][2][4];
        #pragma unroll
        for (int nt = 0; nt < 12; nt++) {
            float2 bb = *(const float2*)&b2s[nt*8 + q*2];
            #pragma unroll
            for (int t = 0; t < 2; t++) {
                acc[nt][t][0] = bb.x; acc[nt][t][1] = bb.y;
                acc[nt][t][2] = bb.x; acc[nt][t][3] = bb.y;
            }
        }

        #pragma unroll
        for (int ks = 0; ks < 4; ks++) {
            // fragment-direct MLP1: build a-fragments for this k-step
            uint32_t ah[2][4], al[2][4];   // [m16 tile][frag slot]
            #pragma unroll
            for (int idx = 0; idx < 2; idx++) {
                int kk = ks*8 + q + idx*4;          // u32 index along k
                float2 wv[5];
                #pragma unroll
                for (int i = 0; i < 5; i++) wv[i] = *(const float2*)&w1s[i*64 + kk*2];
                float2 bb = *(const float2*)&b1s[kk*2];
                #pragma unroll
                for (int m = 0; m < 4; m++) {
                    float d0 = bb.x, d1 = bb.y;
                    #pragma unroll
                    for (int i = 0; i < 5; i++) {
                        d0 = fmaf(xv[m][i], wv[i].x, d0);
                        d1 = fmaf(xv[m][i], wv[i].y, d1);
                    }
                    d0 = elu_fast(d0); d1 = elu_fast(d1);
                    uint16_t h0,l0,h1,l1;
                    bf16split(d0, h0, l0); bf16split(d1, h1, l1);
                    int t = m >> 1, sl = (m & 1) + idx*2;
                    ah[t][sl] = ((uint32_t)h1 << 16) | h0;
                    al[t][sl] = ((uint32_t)l1 << 16) | l0;
                }
            }
            // mma over 12 n-tiles
            int k2 = ks*8 + q;
            #pragma unroll
            for (int nt = 0; nt < 12; nt++) {
                int bi = (nt*8 + r)*36 + k2;
                uint32_t bh[2] = { BH32[bi], BH32[bi+4] };
                uint32_t bl[2] = { BL32[bi], BL32[bi+4] };
                mma16816(acc[nt][0], ah[0], bh);
                mma16816(acc[nt][0], ah[0], bl);
                mma16816(acc[nt][0], al[0], bh);
                mma16816(acc[nt][1], ah[1], bh);
                mma16816(acc[nt][1], ah[1], bl);
                mma16816(acc[nt][1], al[1], bh);
            }
        }

        // --- epilogue: messages + RED.128 scatter from fragments ---
        #pragma unroll
        for (int t = 0; t < 2; t++)
        #pragma unroll
        for (int half = 0; half < 2; half++) {
            int e = wb + r + t*16 + half*8;
            int src = srcs[e], dst = dsts[e];
            float u0 = us[e*3+0], u1 = us[e*3+1], u2 = us[e*3+2];
            const float* srow = g_s + src*Ff;
            const float* p0r = g_v0 + src*Ff;
            const float* p1r = g_v1 + src*Ff;
            const float* p2r = g_v2 + src*Ff;
            float4* arow = g_acc + dst*Ff;
            #pragma unroll
            for (int nt = 0; nt < 4; nt++) {
                int f = nt*8 + q*2;
                float gs0 = acc[nt  ][t][half*2+0], gs1 = acc[nt  ][t][half*2+1];
                float gv0 = acc[nt+4][t][half*2+0], gv1 = acc[nt+4][t][half*2+1];
                float gt0 = acc[nt+8][t][half*2+0], gt1 = acc[nt+8][t][half*2+1];
                float2 ss = *(const float2*)&srow[f];
                float2 p0 = *(const float2*)&p0r[f];
                float2 p1 = *(const float2*)&p1r[f];
                float2 p2 = *(const float2*)&p2r[f];
                float t0 = gt0*ss.x, t1 = gt1*ss.y;
                atomicAdd(&arow[f],
                    make_float4(gs0*ss.x, fmaf(gv0, p0.x, t0*u0),
                                fmaf(gv0, p1.x, t0*u1), fmaf(gv0, p2.x, t0*u2)));
                atomicAdd(&arow[f+1],
                    make_float4(gs1*ss.y, fmaf(gv1, p0.y, t1*u0),
                                fmaf(gv1, p1.y, t1*u1), fmaf(gv1, p2.y, t1*u2)));
            }
        }
    }
}

// ---------------- per-layer node update: residual s,v + acc reset ----------------
__global__ void k_update(const float* __restrict__ Ws, const float* __restrict__ Wv) {
    __shared__ float  wss[1024], wvs[1024];
    __shared__ float4 msh[4][32];
    int tid = threadIdx.x;
    for (int i = tid; i < 1024; i += 128) { wss[i] = Ws[i]; wvs[i] = Wv[i]; }
    __syncthreads();
    int w = tid >> 5, lane = tid & 31;
    int node = blockIdx.x*4 + w;
    if (node >= Nn) return;
    float invd = g_invden[node];
    float4 a = g_acc[node*Ff + lane];
    g_acc[node*Ff + lane] = make_float4(0.f,0.f,0.f,0.f);  // reset for next layer
    msh[w][lane] = make_float4(a.x*invd, a.y*invd, a.z*invd, a.w*invd);
    __syncwarp();
    float so = 0.f, v0 = 0.f, v1 = 0.f, v2 = 0.f;
    #pragma unroll
    for (int f = 0; f < 32; f++) {
        float4 m = msh[w][f];
        float wsv = wss[f*32 + lane];
        float wvv = wvs[f*32 + lane];
        so += m.x*wsv;
        v0 += m.y*wvv; v1 += m.z*wvv; v2 += m.w*wvv;
    }
    int i = node*Ff + lane;
    g_s[i] += elu1(so);
    g_v0[i] += v0; g_v1[i] += v1; g_v2[i] += v2;
}

// ---------------- invariant map + graph pooling (atomic) ----------------
__global__ void k_inv(const float* __restrict__ W_inv, const float* __restrict__ b_inv,
                      const int* __restrict__ batch) {
    __shared__ float wi[64*128];
    __shared__ float bi[128];
    __shared__ float feat[4][64];
    int tid = threadIdx.x;
    for (int i = tid; i < 64*128; i += 128) wi[i] = W_inv[i];
    if (tid < 128) bi[tid] = b_inv[tid];
    __syncthreads();
    int w = tid >> 5, lane = tid & 31;
    int nwarps = gridDim.x*4;
    for (int node = blockIdx.x*4 + w; node < Nn; node += nwarps) {
        int i = node*Ff + lane;
        float sval = g_s[i];
        float a0 = g_v0[i], a1 = g_v1[i], a2 = g_v2[i];
        float vn = sqrtf(a0*a0 + a1*a1 + a2*a2 + EPSf);
        feat[w][lane]      = sval;
        feat[w][32 + lane] = vn;
        __syncwarp();
        int b = batch[node];
        #pragma unroll
        for (int rr = 0; rr < 4; rr++) {
            int c = lane + 32*rr;
            float acc = bi[c];
            #pragma unroll 8
            for (int k = 0; k < 64; k++) acc += feat[w][k] * wi[k*128 + c];
            atomicAdd(&g_xg[b*NINVc + c], acc);
        }
        __syncwarp();
    }
}

// ---------------- head ----------------
__global__ void k_pool_bn1() {
    __shared__ float ssum[256], ssq[256];
    int c = blockIdx.x, tid = threadIdx.x;
    float s = 0.f, q = 0.f;
    for (int g = tid; g < Gc; g += 256) {
        float val = g_xg[g*NINVc + c] / fmaxf(g_gcnt[g], 1.f);
        g_xgp[g*NINVc + c] = val;
        s += val; q += val*val;
    }
    ssum[tid] = s; ssq[tid] = q; __syncthreads();
    for (int st = 128; st > 0; st >>= 1) {
        if (tid < st) { ssum[tid] += ssum[tid+st]; ssq[tid] += ssq[tid+st]; }
        __syncthreads();
    }
    if (tid == 0) {
        float m = ssum[0] / (float)Gc;
        float var = ssq[0] / (float)Gc - m*m;
        g_mean1[c] = m;
        g_rstd1[c] = rsqrtf(var + 1e-5f);
    }
}
__global__ void k_fc1(const float* __restrict__ g1, const float* __restrict__ be1,
                      const float* __restrict__ Wf1, const float* __restrict__ bf1) {
    __shared__ float a[128];
    int g = blockIdx.x, j = threadIdx.x;
    float xv = g_xgp[g*NINVc + j];
    a[j] = elu1((xv - g_mean1[j]) * g_rstd1[j] * g1[j] + be1[j]);
    __syncthreads();
    float acc = bf1[j];
    #pragma unroll 8
    for (int k = 0; k < 128; k++) acc += a[k] * Wf1[k*128 + j];
    g_z1[g*NINVc + j] = acc;
}
__global__ void k_bn2() {
    __shared__ float ssum[256], ssq[256];
    int c = blockIdx.x, tid = threadIdx.x;
    float s = 0.f, q = 0.f;
    for (int g = tid; g < Gc; g += 256) {
        float val = g_z1[g*NINVc + c];
        s += val; q += val*val;
    }
    ssum[tid] = s; ssq[tid] = q; __syncthreads();
    for (int st = 128; st > 0; st >>= 1) {
        if (tid < st) { ssum[tid] += ssum[tid+st]; ssq[tid] += ssq[tid+st]; }
        __syncthreads();
    }
    if (tid == 0) {
        float m = ssum[0] / (float)Gc;
        float var = ssq[0] / (float)Gc - m*m;
        g_mean2[c] = m;
        g_rstd2[c] = rsqrtf(var + 1e-5f);
    }
}
__global__ void k_head(const float* __restrict__ g2, const float* __restrict__ be2,
                       const float* __restrict__ Wf2, const float* __restrict__ bf2,
                       float* __restrict__ out) {
    int w = threadIdx.x >> 5, lane = threadIdx.x & 31;
    int g = blockIdx.x*4 + w;
    if (g >= Gc) return;
    float p = 0.f;
    for (int k = lane; k < 128; k += 32) {
        float zv = g_z1[g*NINVc + k];
        float av = elu1((zv - g_mean2[k]) * g_rstd2[k] * g2[k] + be2[k]);
        p += av * Wf2[k];
    }
    #pragma unroll
    for (int off = 16; off; off >>= 1) p += __shfl_down_sync(0xffffffffu, p, off);
    if (lane == 0) out[g] = p + bf2[0];
}

// ---------------- launch ----------------
extern "C" void kernel_launch(void* const* d_in, const int* in_sizes, int n_in,
                              void* d_out, int out_size) {
    const float* x     = (const float*)d_in[0];
    const float* pos   = (const float*)d_in[1];
    const int*   ei    = (const int*)d_in[2];     // int32 (JAX x64 disabled)
    const float* eattr = (const float*)d_in[3];
    const int*   batch = (const int*)d_in[4];     // int32
    const float* W_es  = (const float*)d_in[5];
    const float* b_es  = (const float*)d_in[6];
    const float* W_ev  = (const float*)d_in[7];
    const float* W1    = (const float*)d_in[8];
    const float* b1    = (const float*)d_in[9];
    const float* W2    = (const float*)d_in[10];
    const float* b2    = (const float*)d_in[11];
    const float* Ws    = (const float*)d_in[12];
    const float* Wv    = (const float*)d_in[13];
    const float* W_inv = (const float*)d_in[14];
    const float* b_inv = (const float*)d_in[15];
    const float* g1    = (const float*)d_in[16];
    const float* be1   = (const float*)d_in[17];
    const float* Wf1   = (const float*)d_in[18];
    const float* bf1   = (const float*)d_in[19];
    const float* g2    = (const float*)d_in[20];
    const float* be2   = (const float*)d_in[21];
    const float* Wf2   = (const float*)d_in[22];
    const float* bf2   = (const float*)d_in[23];
    float* out = (float*)d_out;

    cudaFuncSetAttribute(k_msg_mma, cudaFuncAttributeMaxDynamicSharedMemorySize, TC_SMEM);

    int ztotal = Nn*Ff + Nn + Gc + Gc*NINVc;
    k_zero_all<<<(ztotal + 255)/256, 256>>>();                       // #1
    k_edge_prep<<<(Ee + 255)/256, 256>>>(pos, ei, eattr);            // #2
    k_embed<<<(Nn*Ff + 255)/256, 256>>>(x, pos, W_es, b_es, W_ev);   // #3

    // layer 0 k_msg_mma is launch #4 -> ncu -s 5 -c 1 captures it
    k_msg_mma<<<444, 128, TC_SMEM>>>(W1, b1, W2, b2);                // #4
    k_invden<<<(Nn + 255)/256, 256>>>();                             // #5
    k_update<<<Nn/4, 128>>>(Ws, Wv);                                 // #6

    for (int l = 1; l < NLc; l++) {
        k_msg_mma<<<444, 128, TC_SMEM>>>(W1 + l*5*Hc, b1 + l*Hc,
                                         W2 + l*Hc*3*Ff, b2 + l*3*Ff);
        k_update<<<Nn/4, 128>>>(Ws + l*Ff*Ff, Wv + l*Ff*Ff);
    }

    k_gcnt<<<(Nn + 255)/256, 256>>>(batch);
    k_inv<<<1024, 128>>>(W_inv, b_inv, batch);
    k_pool_bn1<<<NINVc, 256>>>();
    k_fc1<<<Gc, 128>>>(g1, be1, Wf1, bf1);
    k_bn2<<<NINVc, 256>>>();
    k_head<<<Gc/4, 128>>>(g2, be2, Wf2, bf2, out);
}